// round 13
// baseline (speedup 1.0000x reference)
#include <cuda_runtime.h>
#include <cuda_fp16.h>
#include <cstdint>

// ---------------------------------------------------------------------------
// HypergraphAttentionLayer on GB300 (sm_103a), portable-PTX tensor path.
//   h ~= fp16(x) * fp16(W)  (1-chain fp16 HMMA)
//   s1/s2 fused in epilogue; ea[e] = (sum_r s1*(31-r)+s2*r)/496
// R7 kernel bodies + per-WARP dynamic work stealing (atomic ticket = 16-row
// group). Ticket grab hoisted above cp.async wait to hide ATOMG latency.
// Edge kernel resets the ticket counter for the next graph replay.
// ---------------------------------------------------------------------------

#define F_IN   128
#define F_OUT  64
#define DEG    32
#define NPAIRS 496.0f
#define MAX_N  200704
#define PITCHW 68       // 32-bit words per fp16 smem row (64 + 4 pad)
#define PITCHB 272      // bytes per fp16 smem row

__device__ float2 g_s12[MAX_N];
__device__ unsigned int g_ticket;   // reset by edge kernel each invocation

// smem byte offsets
#define SM_AVEC 0                        // 512 B
#define SM_B    512                      // 64*272  = 17408 (fp16 W)
#define SM_A    (SM_B + 17408)           // 128*272 = 34816 (fp16 x, per-warp 16 rows)
#define SM_X0   (SM_A + 34816)           // 8 warps * 2 bufs * 8192 = 131072
#define SM_TOTAL (SM_X0 + 131072)        // 183808 B -> 1 CTA/SM

__device__ __forceinline__ uint32_t smem_u32(const void* p) {
    uint32_t a;
    asm("{ .reg .u64 t; cvta.to.shared.u64 t, %1; cvt.u32.u64 %0, t; }"
        : "=r"(a) : "l"(p));
    return a;
}

__device__ __forceinline__ void mma_f16(float c[4],
                                        uint32_t a0, uint32_t a1,
                                        uint32_t a2, uint32_t a3,
                                        uint32_t b0, uint32_t b1)
{
    asm volatile(
        "mma.sync.aligned.m16n8k16.row.col.f32.f16.f16.f32 "
        "{%0,%1,%2,%3}, {%4,%5,%6,%7}, {%8,%9}, {%0,%1,%2,%3};"
        : "+f"(c[0]), "+f"(c[1]), "+f"(c[2]), "+f"(c[3])
        : "r"(a0), "r"(a1), "r"(a2), "r"(a3), "r"(b0), "r"(b1));
}

__device__ __forceinline__ void ldmatrix_x4(uint32_t& r0, uint32_t& r1,
                                            uint32_t& r2, uint32_t& r3,
                                            uint32_t addr)
{
    asm volatile(
        "ldmatrix.sync.aligned.m8n8.x4.shared.b16 {%0,%1,%2,%3}, [%4];"
        : "=r"(r0), "=r"(r1), "=r"(r2), "=r"(r3) : "r"(addr));
}

__device__ __forceinline__ uint2 pack_h4(float4 v) {
    __half2 p01 = __floats2half2_rn(v.x, v.y);
    __half2 p23 = __floats2half2_rn(v.z, v.w);
    uint2 pk;
    pk.x = *reinterpret_cast<uint32_t*>(&p01);
    pk.y = *reinterpret_cast<uint32_t*>(&p23);
    return pk;
}

// ---------------------------------------------------------------------------
// Persistent GEMM: grid = #SMs, 256 threads (8 warps). Work unit = 16 rows,
// claimed per-warp from a global ticket counter. Warp-autonomous pipeline.
// ---------------------------------------------------------------------------
__global__ __launch_bounds__(256, 1)
void gemm_persist_kernel(const float* __restrict__ x,
                         const float* __restrict__ W,
                         const float* __restrict__ a,
                         float* __restrict__ h_out,
                         int N, int NT)          // NT = N/16 row-groups
{
    extern __shared__ char smem[];
    float*    As = reinterpret_cast<float*>(smem + SM_AVEC);
    uint32_t* B  = reinterpret_cast<uint32_t*>(smem + SM_B);
    uint32_t* A  = reinterpret_cast<uint32_t*>(smem + SM_A);

    const int tid  = threadIdx.x;
    const int wid  = tid >> 5;
    const int lane = tid & 31;
    const int qr   = lane >> 2;
    const int qc   = lane & 3;

    const uint32_t xw_u32 = smem_u32(smem + SM_X0) + (uint32_t)wid * 16384u;

    // per-warp ticket grab (lane 0 atomic, broadcast)
    auto grab = [&]() -> int {
        unsigned int t = 0;
        if (lane == 0) t = atomicAdd(&g_ticket, 1u);
        return (int)__shfl_sync(0xFFFFFFFFu, t, 0);
    };

    // copy 16 rows (group t) into buffer b; ALWAYS commits one group
    auto issue_copy = [&](int t, int b) {
        if (t < NT) {
            uint32_t base = xw_u32 + (uint32_t)b * 8192u;
            const float4* src =
                reinterpret_cast<const float4*>(x) + (size_t)t * 16 * 32;
#pragma unroll
            for (int it = 0; it < 16; ++it) {
                int idx = it * 32 + lane;       // 512 float4
                asm volatile("cp.async.cg.shared.global [%0], [%1], 16;"
                             :: "r"(base + (uint32_t)idx * 16u),
                                "l"(src + idx) : "memory");
            }
        }
        asm volatile("cp.async.commit_group;" ::: "memory");
    };

    int t0 = grab();
    int t1 = grab();
    issue_copy(t0, 0);
    issue_copy(t1, 1);

    // ---- W (64x128 fp32) -> fp16 smem, once per CTA ----
#pragma unroll
    for (int it = 0; it < 8; ++it) {
        int idx = it * 256 + tid;
        int n   = idx >> 5;
        int c4  = idx & 31;
        float4 v = reinterpret_cast<const float4*>(W)[n * 32 + c4];
        *reinterpret_cast<uint2*>(B + n * PITCHW + c4 * 2) = pack_h4(v);
    }
    if (tid < 2 * F_OUT) As[tid] = a[tid];
    __syncthreads();

    // ---- all B fragments -> registers (held for whole kernel) ----
    uint32_t bf[8][8][2];
    {
        int rowselB  = (lane & 7) + ((lane >> 4) & 1) * 8;
        int byteselB = ((lane >> 3) & 1) * 16;
        uint32_t b_base = smem_u32(smem + SM_B) + rowselB * PITCHB + byteselB;
#pragma unroll
        for (int jp = 0; jp < 4; ++jp)
#pragma unroll
            for (int kk = 0; kk < 8; ++kk)
                ldmatrix_x4(bf[kk][2 * jp][0], bf[kk][2 * jp][1],
                            bf[kk][2 * jp + 1][0], bf[kk][2 * jp + 1][1],
                            b_base + jp * 16 * PITCHB + kk * 32);
    }

    const int rowselA  = (lane & 7) + ((lane >> 3) & 1) * 8;
    const int byteselA = ((lane >> 4) & 1) * 16;
    const uint32_t a_base = smem_u32(smem + SM_A) +
        (wid * 16 + rowselA) * PITCHB + byteselA;

    // ---- warp-autonomous work-stealing loop ----
    int buf = 0;
    while (t0 < NT) {
        // grab next ticket EARLY: ATOMG latency hides under wait_group
        int t2 = grab();

        // oldest pending group is buf's (in-order completion)
        asm volatile("cp.async.wait_group 1;" ::: "memory");

        // convert my 16 rows -> A slice
        const float4* Xb = reinterpret_cast<const float4*>(
            smem + SM_X0 + wid * 16384 + buf * 8192);
        uint32_t* Aw = A + wid * 16 * PITCHW;
#pragma unroll
        for (int it = 0; it < 16; ++it) {
            int idx = it * 32 + lane;
            *reinterpret_cast<uint2*>(
                Aw + (idx >> 5) * PITCHW + (idx & 31) * 2) = pack_h4(Xb[idx]);
        }
        __syncwarp();

        issue_copy(t2, buf);

        // ---- MMA: 8 k16 steps x 8 n-frags ----
        float c[8][4];
#pragma unroll
        for (int j = 0; j < 8; ++j)
#pragma unroll
            for (int q = 0; q < 4; ++q) c[j][q] = 0.f;

#pragma unroll
        for (int kk = 0; kk < 8; ++kk) {
            uint32_t a0, a1, a2, a3;
            ldmatrix_x4(a0, a1, a2, a3, a_base + kk * 32);
#pragma unroll
            for (int j = 0; j < 8; ++j)
                mma_f16(c[j], a0, a1, a2, a3, bf[kk][j][0], bf[kk][j][1]);
        }

        // ---- epilogue: rows t0*16 .. +16 ----
        {
            float s1a = 0.f, s2a = 0.f, s1b = 0.f, s2b = 0.f;
            int ra = t0 * 16 + qr;
            int rb = ra + 8;
#pragma unroll
            for (int j = 0; j < 8; ++j) {
                int n = j * 8 + qc * 2;
                float a1v = As[n],         a2v = As[n + 1];
                float b1v = As[F_OUT + n], b2v = As[F_OUT + n + 1];
                float* cc = c[j];
                if (ra < N)
                    *reinterpret_cast<float2*>(h_out + (size_t)ra * F_OUT + n) =
                        make_float2(cc[0], cc[1]);
                if (rb < N)
                    *reinterpret_cast<float2*>(h_out + (size_t)rb * F_OUT + n) =
                        make_float2(cc[2], cc[3]);
                s1a = fmaf(cc[0], a1v, fmaf(cc[1], a2v, s1a));
                s2a = fmaf(cc[0], b1v, fmaf(cc[1], b2v, s2a));
                s1b = fmaf(cc[2], a1v, fmaf(cc[3], a2v, s1b));
                s2b = fmaf(cc[2], b1v, fmaf(cc[3], b2v, s2b));
            }
#pragma unroll
            for (int off = 1; off <= 2; off <<= 1) {
                s1a += __shfl_xor_sync(0xFFFFFFFFu, s1a, off);
                s2a += __shfl_xor_sync(0xFFFFFFFFu, s2a, off);
                s1b += __shfl_xor_sync(0xFFFFFFFFu, s1b, off);
                s2b += __shfl_xor_sync(0xFFFFFFFFu, s2b, off);
            }
            if (qc == 0) {
                if (ra < N) g_s12[ra] = make_float2(s1a, s2a);
                if (rb < N) g_s12[rb] = make_float2(s1b, s2b);
            }
        }

        t0 = t1;
        t1 = t2;
        buf ^= 1;
    }
}

// ---------------------------------------------------------------------------
// Edge attention: one warp = 8 edges (L1tex replay-floor shape, ~10.5us).
// Also resets the GEMM ticket counter for the next graph replay (safe: this
// kernel is stream-ordered after the GEMM of the same invocation).
// ---------------------------------------------------------------------------
__global__ __launch_bounds__(256)
void edge_attn_kernel(const int* __restrict__ nodes,
                      float* __restrict__ ea_out,
                      int H)
{
    if (blockIdx.x == 0 && threadIdx.x == 0) g_ticket = 0u;

    int gw   = (blockIdx.x * 256 + threadIdx.x) >> 5;
    int lane = threadIdx.x & 31;
    int e0   = gw * 8;
    if (e0 >= H) return;

    if (e0 + 8 <= H) {
        const int4* base = reinterpret_cast<const int4*>(nodes + (size_t)e0 * DEG);
        int4 n0 = base[lane];
        int4 n1 = base[32 + lane];
        int r0 = (lane & 7) * 4;

        float2 s00 = g_s12[n0.x], s01 = g_s12[n0.y];
        float2 s02 = g_s12[n0.z], s03 = g_s12[n0.w];
        float2 s10 = g_s12[n1.x], s11 = g_s12[n1.y];
        float2 s12v = g_s12[n1.z], s13 = g_s12[n1.w];

        float fl = (float)(31 - r0), fr = (float)r0;
        float v0 = s00.x * fl         + s00.y * fr
                 + s01.x * (fl - 1.f) + s01.y * (fr + 1.f)
                 + s02.x * (fl - 2.f) + s02.y * (fr + 2.f)
                 + s03.x * (fl - 3.f) + s03.y * (fr + 3.f);
        float v1 = s10.x * fl         + s10.y * fr
                 + s11.x * (fl - 1.f) + s11.y * (fr + 1.f)
                 + s12v.x * (fl - 2.f) + s12v.y * (fr + 2.f)
                 + s13.x * (fl - 3.f) + s13.y * (fr + 3.f);

#pragma unroll
        for (int off = 1; off <= 4; off <<= 1) {
            v0 += __shfl_xor_sync(0xFFFFFFFFu, v0, off);
            v1 += __shfl_xor_sync(0xFFFFFFFFu, v1, off);
        }
        if ((lane & 7) == 0) {
            int eg = e0 + (lane >> 3);
            ea_out[eg]     = v0 * (1.0f / NPAIRS);
            ea_out[eg + 4] = v1 * (1.0f / NPAIRS);
        }
    } else {
        for (int i = 0; i < 8; ++i) {
            int e = e0 + i;
            if (e >= H) break;
            int node = nodes[(size_t)e * DEG + lane];
            float2 s = g_s12[node];
            float v = s.x * (float)(DEG - 1 - lane) + s.y * (float)lane;
#pragma unroll
            for (int off = 16; off > 0; off >>= 1)
                v += __shfl_xor_sync(0xFFFFFFFFu, v, off);
            if (lane == 0) ea_out[e] = v * (1.0f / NPAIRS);
        }
    }
}

// ---------------------------------------------------------------------------
extern "C" void kernel_launch(void* const* d_in, const int* in_sizes, int n_in,
                              void* d_out, int out_size)
{
    const float* x    = (const float*)d_in[0];
    const float* W    = (const float*)d_in[1];
    const float* a    = (const float*)d_in[2];
    const int*   hidx = (const int*)d_in[3];

    int N = in_sizes[0] / F_IN;    // 200000
    int E = in_sizes[3] / 2;       // 1,600,000
    int H = E / DEG;               // 50000

    float* h_out  = (float*)d_out;
    float* ea_out = (float*)d_out + (size_t)N * F_OUT;
    const int* nodes = hidx;

    int sms = 0;
    cudaDeviceGetAttribute(&sms, cudaDevAttrMultiProcessorCount, 0);
    if (sms <= 0) sms = 148;

    cudaFuncSetAttribute(gemm_persist_kernel,
                         cudaFuncAttributeMaxDynamicSharedMemorySize, SM_TOTAL);

    int NT = (N + 15) / 16;                   // 12500 row-groups
    gemm_persist_kernel<<<sms, 256, SM_TOTAL>>>(x, W, a, h_out, N, NT);

    {
        int warps  = (H + 7) / 8;             // 6250
        int blocks = (warps * 32 + 255) / 256;
        edge_attn_kernel<<<blocks, 256>>>(nodes, ea_out, H);
    }
}

// round 14
// speedup vs baseline: 1.1011x; 1.1011x over previous
#include <cuda_runtime.h>
#include <cuda_fp16.h>
#include <cstdint>

// ---------------------------------------------------------------------------
// HypergraphAttentionLayer on GB300 (sm_103a), portable-PTX tensor path.
//   h ~= fp16(x) * fp16(W)   (1-chain fp16 HMMA)
//   s1/s2 fused in epilogue; ea[e] = (sum_r s1*(31-r)+s2*r)/496
// Persistent warp-autonomous GEMM. W fragments held in REGISTERS for the
// whole kernel (loaded once via ldmatrix); A fragments via ldmatrix.x4.
// [R7 configuration — measured optimum: GEMM ~26.3us @ DRAM ceiling,
//  edge ~10.5us @ L1tex gather-wavefront floor.]
// ---------------------------------------------------------------------------

#define F_IN   128
#define F_OUT  64
#define DEG    32
#define NPAIRS 496.0f
#define MAX_N  200704
#define TILE_M 128
#define PITCHW 68       // 32-bit words per fp16 smem row (64 + 4 pad)
#define PITCHB 272      // bytes per fp16 smem row

__device__ float2 g_s12[MAX_N];

// smem byte offsets
#define SM_AVEC 0                        // 512 B
#define SM_B    512                      // 64*272  = 17408 (fp16 W)
#define SM_A    (SM_B + 17408)           // 128*272 = 34816 (fp16 x)
#define SM_X0   (SM_A + 34816)           // 8 warps * 2 bufs * 8192 = 131072
#define SM_TOTAL (SM_X0 + 131072)        // 183808 B -> 1 CTA/SM

__device__ __forceinline__ uint32_t smem_u32(const void* p) {
    uint32_t a;
    asm("{ .reg .u64 t; cvta.to.shared.u64 t, %1; cvt.u32.u64 %0, t; }"
        : "=r"(a) : "l"(p));
    return a;
}

__device__ __forceinline__ void mma_f16(float c[4],
                                        uint32_t a0, uint32_t a1,
                                        uint32_t a2, uint32_t a3,
                                        uint32_t b0, uint32_t b1)
{
    asm volatile(
        "mma.sync.aligned.m16n8k16.row.col.f32.f16.f16.f32 "
        "{%0,%1,%2,%3}, {%4,%5,%6,%7}, {%8,%9}, {%0,%1,%2,%3};"
        : "+f"(c[0]), "+f"(c[1]), "+f"(c[2]), "+f"(c[3])
        : "r"(a0), "r"(a1), "r"(a2), "r"(a3), "r"(b0), "r"(b1));
}

__device__ __forceinline__ void ldmatrix_x4(uint32_t& r0, uint32_t& r1,
                                            uint32_t& r2, uint32_t& r3,
                                            uint32_t addr)
{
    asm volatile(
        "ldmatrix.sync.aligned.m8n8.x4.shared.b16 {%0,%1,%2,%3}, [%4];"
        : "=r"(r0), "=r"(r1), "=r"(r2), "=r"(r3) : "r"(addr));
}

__device__ __forceinline__ uint2 pack_h4(float4 v) {
    __half2 p01 = __floats2half2_rn(v.x, v.y);
    __half2 p23 = __floats2half2_rn(v.z, v.w);
    uint2 pk;
    pk.x = *reinterpret_cast<uint32_t*>(&p01);
    pk.y = *reinterpret_cast<uint32_t*>(&p23);
    return pk;
}

// ---------------------------------------------------------------------------
// Persistent GEMM: grid = #SMs, 256 threads (8 warps). Warp w owns rows
// [t*128 + w*16, +16); self-pipelined cp.async; B frags in registers.
// ---------------------------------------------------------------------------
__global__ __launch_bounds__(256, 1)
void gemm_persist_kernel(const float* __restrict__ x,
                         const float* __restrict__ W,
                         const float* __restrict__ a,
                         float* __restrict__ h_out,
                         int N, int tiles)
{
    extern __shared__ char smem[];
    float*    As = reinterpret_cast<float*>(smem + SM_AVEC);
    uint32_t* B  = reinterpret_cast<uint32_t*>(smem + SM_B);
    uint32_t* A  = reinterpret_cast<uint32_t*>(smem + SM_A);

    const int tid  = threadIdx.x;
    const int wid  = tid >> 5;
    const int lane = tid & 31;
    const int qr   = lane >> 2;
    const int qc   = lane & 3;
    const int g    = gridDim.x;

    const uint32_t xw_u32 = smem_u32(smem + SM_X0) + (uint32_t)wid * 16384u;

    auto issue_copy = [&](int row0, int b) {
        uint32_t base = xw_u32 + (uint32_t)b * 8192u;
        int r0 = row0 + wid * 16;
#pragma unroll
        for (int it = 0; it < 16; ++it) {
            int idx = it * 32 + lane;
            int rg  = r0 + (idx >> 5);
            if (rg >= N) rg = N - 1;
            const float4* src =
                reinterpret_cast<const float4*>(x) + (size_t)rg * 32 + (idx & 31);
            asm volatile("cp.async.cg.shared.global [%0], [%1], 16;"
                         :: "r"(base + (uint32_t)idx * 16u), "l"(src) : "memory");
        }
        asm volatile("cp.async.commit_group;" ::: "memory");
    };

    if (blockIdx.x < tiles)     issue_copy(blockIdx.x * TILE_M, 0);
    if (blockIdx.x + g < tiles) issue_copy((blockIdx.x + g) * TILE_M, 1);

    // ---- W (64x128 fp32) -> fp16 smem, once per CTA ----
#pragma unroll
    for (int it = 0; it < 8; ++it) {
        int idx = it * 256 + tid;
        int n   = idx >> 5;
        int c4  = idx & 31;
        float4 v = reinterpret_cast<const float4*>(W)[n * 32 + c4];
        *reinterpret_cast<uint2*>(B + n * PITCHW + c4 * 2) = pack_h4(v);
    }
    if (tid < 2 * F_OUT) As[tid] = a[tid];
    __syncthreads();

    // ---- all B fragments -> registers (held for whole kernel) ----
    uint32_t bf[8][8][2];
    {
        int rowselB  = (lane & 7) + ((lane >> 4) & 1) * 8;
        int byteselB = ((lane >> 3) & 1) * 16;
        uint32_t b_base = smem_u32(smem + SM_B) + rowselB * PITCHB + byteselB;
#pragma unroll
        for (int jp = 0; jp < 4; ++jp)
#pragma unroll
            for (int kk = 0; kk < 8; ++kk)
                ldmatrix_x4(bf[kk][2 * jp][0], bf[kk][2 * jp][1],
                            bf[kk][2 * jp + 1][0], bf[kk][2 * jp + 1][1],
                            b_base + jp * 16 * PITCHB + kk * 32);
    }

    const int rowselA  = (lane & 7) + ((lane >> 3) & 1) * 8;
    const int byteselA = ((lane >> 4) & 1) * 16;
    const uint32_t a_base = smem_u32(smem + SM_A) +
        (wid * 16 + rowselA) * PITCHB + byteselA;

    // ---- warp-autonomous persistent loop ----
    int buf = 0;
    for (int t = blockIdx.x; t < tiles; t += g, buf ^= 1) {
        const int row0 = t * TILE_M;

        if (t + g < tiles)
            asm volatile("cp.async.wait_group 1;" ::: "memory");
        else
            asm volatile("cp.async.wait_group 0;" ::: "memory");

        // convert my Xraw[buf] -> my A slice
        const float4* Xb = reinterpret_cast<const float4*>(
            smem + SM_X0 + wid * 16384 + buf * 8192);
        uint32_t* Aw = A + wid * 16 * PITCHW;
#pragma unroll
        for (int it = 0; it < 16; ++it) {
            int idx = it * 32 + lane;
            *reinterpret_cast<uint2*>(
                Aw + (idx >> 5) * PITCHW + (idx & 31) * 2) = pack_h4(Xb[idx]);
        }
        __syncwarp();

        if (t + 2 * g < tiles) issue_copy((t + 2 * g) * TILE_M, buf);

        // ---- MMA: ldmatrix A frags, B frags from registers ----
        float c[8][4];
#pragma unroll
        for (int j = 0; j < 8; ++j)
#pragma unroll
            for (int q = 0; q < 4; ++q) c[j][q] = 0.f;

#pragma unroll
        for (int kk = 0; kk < 8; ++kk) {
            uint32_t a0, a1, a2, a3;
            ldmatrix_x4(a0, a1, a2, a3, a_base + kk * 32);
#pragma unroll
            for (int j = 0; j < 8; ++j)
                mma_f16(c[j], a0, a1, a2, a3, bf[kk][j][0], bf[kk][j][1]);
        }

        // ---- epilogue: write h, fold s1/s2 ----
        {
            float s1a = 0.f, s2a = 0.f, s1b = 0.f, s2b = 0.f;
            int ra = row0 + wid * 16 + qr;
            int rb = ra + 8;
#pragma unroll
            for (int j = 0; j < 8; ++j) {
                int n = j * 8 + qc * 2;
                float a1v = As[n],         a2v = As[n + 1];
                float b1v = As[F_OUT + n], b2v = As[F_OUT + n + 1];
                float* cc = c[j];
                if (ra < N)
                    *reinterpret_cast<float2*>(h_out + (size_t)ra * F_OUT + n) =
                        make_float2(cc[0], cc[1]);
                if (rb < N)
                    *reinterpret_cast<float2*>(h_out + (size_t)rb * F_OUT + n) =
                        make_float2(cc[2], cc[3]);
                s1a = fmaf(cc[0], a1v, fmaf(cc[1], a2v, s1a));
                s2a = fmaf(cc[0], b1v, fmaf(cc[1], b2v, s2a));
                s1b = fmaf(cc[2], a1v, fmaf(cc[3], a2v, s1b));
                s2b = fmaf(cc[2], b1v, fmaf(cc[3], b2v, s2b));
            }
#pragma unroll
            for (int off = 1; off <= 2; off <<= 1) {
                s1a += __shfl_xor_sync(0xFFFFFFFFu, s1a, off);
                s2a += __shfl_xor_sync(0xFFFFFFFFu, s2a, off);
                s1b += __shfl_xor_sync(0xFFFFFFFFu, s1b, off);
                s2b += __shfl_xor_sync(0xFFFFFFFFu, s2b, off);
            }
            if (qc == 0) {
                if (ra < N) g_s12[ra] = make_float2(s1a, s2a);
                if (rb < N) g_s12[rb] = make_float2(s1b, s2b);
            }
        }
    }
}

// ---------------------------------------------------------------------------
// Edge attention: one warp = 8 edges. Two LDG.128 fetch 256 node ids;
// each lane gathers 8 float2 (one 8B gather per incidence — minimal);
// reduce over 8-lane groups (3 shuffles).
// ---------------------------------------------------------------------------
__global__ __launch_bounds__(256)
void edge_attn_kernel(const int* __restrict__ nodes,
                      float* __restrict__ ea_out,
                      int H)
{
    int gw   = (blockIdx.x * 256 + threadIdx.x) >> 5;
    int lane = threadIdx.x & 31;
    int e0   = gw * 8;
    if (e0 >= H) return;

    if (e0 + 8 <= H) {
        const int4* base = reinterpret_cast<const int4*>(nodes + (size_t)e0 * DEG);
        int4 n0 = base[lane];        // edge e0 +     (lane>>3), ranks r0..r0+3
        int4 n1 = base[32 + lane];   // edge e0 + 4 + (lane>>3), ranks r0..r0+3
        int r0 = (lane & 7) * 4;

        float2 s00 = g_s12[n0.x], s01 = g_s12[n0.y];
        float2 s02 = g_s12[n0.z], s03 = g_s12[n0.w];
        float2 s10 = g_s12[n1.x], s11 = g_s12[n1.y];
        float2 s12v = g_s12[n1.z], s13 = g_s12[n1.w];

        float fl = (float)(31 - r0), fr = (float)r0;
        float v0 = s00.x * fl         + s00.y * fr
                 + s01.x * (fl - 1.f) + s01.y * (fr + 1.f)
                 + s02.x * (fl - 2.f) + s02.y * (fr + 2.f)
                 + s03.x * (fl - 3.f) + s03.y * (fr + 3.f);
        float v1 = s10.x * fl         + s10.y * fr
                 + s11.x * (fl - 1.f) + s11.y * (fr + 1.f)
                 + s12v.x * (fl - 2.f) + s12v.y * (fr + 2.f)
                 + s13.x * (fl - 3.f) + s13.y * (fr + 3.f);

#pragma unroll
        for (int off = 1; off <= 4; off <<= 1) {
            v0 += __shfl_xor_sync(0xFFFFFFFFu, v0, off);
            v1 += __shfl_xor_sync(0xFFFFFFFFu, v1, off);
        }
        if ((lane & 7) == 0) {
            int eg = e0 + (lane >> 3);
            ea_out[eg]     = v0 * (1.0f / NPAIRS);
            ea_out[eg + 4] = v1 * (1.0f / NPAIRS);
        }
    } else {
        for (int i = 0; i < 8; ++i) {
            int e = e0 + i;
            if (e >= H) break;
            int node = nodes[(size_t)e * DEG + lane];
            float2 s = g_s12[node];
            float v = s.x * (float)(DEG - 1 - lane) + s.y * (float)lane;
#pragma unroll
            for (int off = 16; off > 0; off >>= 1)
                v += __shfl_xor_sync(0xFFFFFFFFu, v, off);
            if (lane == 0) ea_out[e] = v * (1.0f / NPAIRS);
        }
    }
}

// ---------------------------------------------------------------------------
extern "C" void kernel_launch(void* const* d_in, const int* in_sizes, int n_in,
                              void* d_out, int out_size)
{
    const float* x    = (const float*)d_in[0];
    const float* W    = (const float*)d_in[1];
    const float* a    = (const float*)d_in[2];
    const int*   hidx = (const int*)d_in[3];

    int N = in_sizes[0] / F_IN;    // 200000
    int E = in_sizes[3] / 2;       // 1,600,000
    int H = E / DEG;               // 50000

    float* h_out  = (float*)d_out;
    float* ea_out = (float*)d_out + (size_t)N * F_OUT;
    const int* nodes = hidx;

    int sms = 0;
    cudaDeviceGetAttribute(&sms, cudaDevAttrMultiProcessorCount, 0);
    if (sms <= 0) sms = 148;

    cudaFuncSetAttribute(gemm_persist_kernel,
                         cudaFuncAttributeMaxDynamicSharedMemorySize, SM_TOTAL);

    int tiles = (N + TILE_M - 1) / TILE_M;    // 1563
    gemm_persist_kernel<<<sms, 256, SM_TOTAL>>>(x, W, a, h_out, N, tiles);

    {
        int warps  = (H + 7) / 8;             // 6250
        int blocks = (warps * 32 + 255) / 256;
        edge_attn_kernel<<<blocks, 256>>>(nodes, ea_out, H);
    }
}

// round 15
// speedup vs baseline: 1.1240x; 1.0208x over previous
#include <cuda_runtime.h>
#include <cuda_fp16.h>
#include <cstdint>

// ---------------------------------------------------------------------------
// HypergraphAttentionLayer on GB300 (sm_103a), portable-PTX tensor path.
//   h ~= fp16(x) * fp16(W)   (1-chain fp16 HMMA)
//   s1/s2 fused in epilogue; ea[e] = (sum_r s1*(31-r)+s2*r)/496
// R7 configuration + st.global.cs (evict-first) on the h output stream:
// h is write-once/never-reread, so keep it out of L2 and preserve the
// g_s12 table residency for the edge kernel's gathers.
// ---------------------------------------------------------------------------

#define F_IN   128
#define F_OUT  64
#define DEG    32
#define NPAIRS 496.0f
#define MAX_N  200704
#define TILE_M 128
#define PITCHW 68       // 32-bit words per fp16 smem row (64 + 4 pad)
#define PITCHB 272      // bytes per fp16 smem row

__device__ float2 g_s12[MAX_N];

// smem byte offsets
#define SM_AVEC 0                        // 512 B
#define SM_B    512                      // 64*272  = 17408 (fp16 W)
#define SM_A    (SM_B + 17408)           // 128*272 = 34816 (fp16 x)
#define SM_X0   (SM_A + 34816)           // 8 warps * 2 bufs * 8192 = 131072
#define SM_TOTAL (SM_X0 + 131072)        // 183808 B -> 1 CTA/SM

__device__ __forceinline__ uint32_t smem_u32(const void* p) {
    uint32_t a;
    asm("{ .reg .u64 t; cvta.to.shared.u64 t, %1; cvt.u32.u64 %0, t; }"
        : "=r"(a) : "l"(p));
    return a;
}

__device__ __forceinline__ void mma_f16(float c[4],
                                        uint32_t a0, uint32_t a1,
                                        uint32_t a2, uint32_t a3,
                                        uint32_t b0, uint32_t b1)
{
    asm volatile(
        "mma.sync.aligned.m16n8k16.row.col.f32.f16.f16.f32 "
        "{%0,%1,%2,%3}, {%4,%5,%6,%7}, {%8,%9}, {%0,%1,%2,%3};"
        : "+f"(c[0]), "+f"(c[1]), "+f"(c[2]), "+f"(c[3])
        : "r"(a0), "r"(a1), "r"(a2), "r"(a3), "r"(b0), "r"(b1));
}

__device__ __forceinline__ void ldmatrix_x4(uint32_t& r0, uint32_t& r1,
                                            uint32_t& r2, uint32_t& r3,
                                            uint32_t addr)
{
    asm volatile(
        "ldmatrix.sync.aligned.m8n8.x4.shared.b16 {%0,%1,%2,%3}, [%4];"
        : "=r"(r0), "=r"(r1), "=r"(r2), "=r"(r3) : "r"(addr));
}

__device__ __forceinline__ uint2 pack_h4(float4 v) {
    __half2 p01 = __floats2half2_rn(v.x, v.y);
    __half2 p23 = __floats2half2_rn(v.z, v.w);
    uint2 pk;
    pk.x = *reinterpret_cast<uint32_t*>(&p01);
    pk.y = *reinterpret_cast<uint32_t*>(&p23);
    return pk;
}

// streaming (evict-first) float2 store for the write-once h tensor
__device__ __forceinline__ void stg_cs_f2(float* p, float lo, float hi) {
    asm volatile("st.global.cs.v2.f32 [%0], {%1, %2};"
                 :: "l"(p), "f"(lo), "f"(hi) : "memory");
}

// ---------------------------------------------------------------------------
// Persistent GEMM: grid = #SMs, 256 threads (8 warps). Warp w owns rows
// [t*128 + w*16, +16); self-pipelined cp.async; B frags in registers.
// ---------------------------------------------------------------------------
__global__ __launch_bounds__(256, 1)
void gemm_persist_kernel(const float* __restrict__ x,
                         const float* __restrict__ W,
                         const float* __restrict__ a,
                         float* __restrict__ h_out,
                         int N, int tiles)
{
    extern __shared__ char smem[];
    float*    As = reinterpret_cast<float*>(smem + SM_AVEC);
    uint32_t* B  = reinterpret_cast<uint32_t*>(smem + SM_B);
    uint32_t* A  = reinterpret_cast<uint32_t*>(smem + SM_A);

    const int tid  = threadIdx.x;
    const int wid  = tid >> 5;
    const int lane = tid & 31;
    const int qr   = lane >> 2;
    const int qc   = lane & 3;
    const int g    = gridDim.x;

    const uint32_t xw_u32 = smem_u32(smem + SM_X0) + (uint32_t)wid * 16384u;

    auto issue_copy = [&](int row0, int b) {
        uint32_t base = xw_u32 + (uint32_t)b * 8192u;
        int r0 = row0 + wid * 16;
#pragma unroll
        for (int it = 0; it < 16; ++it) {
            int idx = it * 32 + lane;
            int rg  = r0 + (idx >> 5);
            if (rg >= N) rg = N - 1;
            const float4* src =
                reinterpret_cast<const float4*>(x) + (size_t)rg * 32 + (idx & 31);
            asm volatile("cp.async.cg.shared.global [%0], [%1], 16;"
                         :: "r"(base + (uint32_t)idx * 16u), "l"(src) : "memory");
        }
        asm volatile("cp.async.commit_group;" ::: "memory");
    };

    if (blockIdx.x < tiles)     issue_copy(blockIdx.x * TILE_M, 0);
    if (blockIdx.x + g < tiles) issue_copy((blockIdx.x + g) * TILE_M, 1);

    // ---- W (64x128 fp32) -> fp16 smem, once per CTA ----
#pragma unroll
    for (int it = 0; it < 8; ++it) {
        int idx = it * 256 + tid;
        int n   = idx >> 5;
        int c4  = idx & 31;
        float4 v = reinterpret_cast<const float4*>(W)[n * 32 + c4];
        *reinterpret_cast<uint2*>(B + n * PITCHW + c4 * 2) = pack_h4(v);
    }
    if (tid < 2 * F_OUT) As[tid] = a[tid];
    __syncthreads();

    // ---- all B fragments -> registers (held for whole kernel) ----
    uint32_t bf[8][8][2];
    {
        int rowselB  = (lane & 7) + ((lane >> 4) & 1) * 8;
        int byteselB = ((lane >> 3) & 1) * 16;
        uint32_t b_base = smem_u32(smem + SM_B) + rowselB * PITCHB + byteselB;
#pragma unroll
        for (int jp = 0; jp < 4; ++jp)
#pragma unroll
            for (int kk = 0; kk < 8; ++kk)
                ldmatrix_x4(bf[kk][2 * jp][0], bf[kk][2 * jp][1],
                            bf[kk][2 * jp + 1][0], bf[kk][2 * jp + 1][1],
                            b_base + jp * 16 * PITCHB + kk * 32);
    }

    const int rowselA  = (lane & 7) + ((lane >> 3) & 1) * 8;
    const int byteselA = ((lane >> 4) & 1) * 16;
    const uint32_t a_base = smem_u32(smem + SM_A) +
        (wid * 16 + rowselA) * PITCHB + byteselA;

    // ---- warp-autonomous persistent loop ----
    int buf = 0;
    for (int t = blockIdx.x; t < tiles; t += g, buf ^= 1) {
        const int row0 = t * TILE_M;

        if (t + g < tiles)
            asm volatile("cp.async.wait_group 1;" ::: "memory");
        else
            asm volatile("cp.async.wait_group 0;" ::: "memory");

        // convert my Xraw[buf] -> my A slice
        const float4* Xb = reinterpret_cast<const float4*>(
            smem + SM_X0 + wid * 16384 + buf * 8192);
        uint32_t* Aw = A + wid * 16 * PITCHW;
#pragma unroll
        for (int it = 0; it < 16; ++it) {
            int idx = it * 32 + lane;
            *reinterpret_cast<uint2*>(
                Aw + (idx >> 5) * PITCHW + (idx & 31) * 2) = pack_h4(Xb[idx]);
        }
        __syncwarp();

        if (t + 2 * g < tiles) issue_copy((t + 2 * g) * TILE_M, buf);

        // ---- MMA: ldmatrix A frags, B frags from registers ----
        float c[8][4];
#pragma unroll
        for (int j = 0; j < 8; ++j)
#pragma unroll
            for (int q = 0; q < 4; ++q) c[j][q] = 0.f;

#pragma unroll
        for (int kk = 0; kk < 8; ++kk) {
            uint32_t a0, a1, a2, a3;
            ldmatrix_x4(a0, a1, a2, a3, a_base + kk * 32);
#pragma unroll
            for (int j = 0; j < 8; ++j)
                mma_f16(c[j], a0, a1, a2, a3, bf[kk][j][0], bf[kk][j][1]);
        }

        // ---- epilogue: write h (streaming), fold s1/s2 ----
        {
            float s1a = 0.f, s2a = 0.f, s1b = 0.f, s2b = 0.f;
            int ra = row0 + wid * 16 + qr;
            int rb = ra + 8;
#pragma unroll
            for (int j = 0; j < 8; ++j) {
                int n = j * 8 + qc * 2;
                float a1v = As[n],         a2v = As[n + 1];
                float b1v = As[F_OUT + n], b2v = As[F_OUT + n + 1];
                float* cc = c[j];
                if (ra < N)
                    stg_cs_f2(h_out + (size_t)ra * F_OUT + n, cc[0], cc[1]);
                if (rb < N)
                    stg_cs_f2(h_out + (size_t)rb * F_OUT + n, cc[2], cc[3]);
                s1a = fmaf(cc[0], a1v, fmaf(cc[1], a2v, s1a));
                s2a = fmaf(cc[0], b1v, fmaf(cc[1], b2v, s2a));
                s1b = fmaf(cc[2], a1v, fmaf(cc[3], a2v, s1b));
                s2b = fmaf(cc[2], b1v, fmaf(cc[3], b2v, s2b));
            }
#pragma unroll
            for (int off = 1; off <= 2; off <<= 1) {
                s1a += __shfl_xor_sync(0xFFFFFFFFu, s1a, off);
                s2a += __shfl_xor_sync(0xFFFFFFFFu, s2a, off);
                s1b += __shfl_xor_sync(0xFFFFFFFFu, s1b, off);
                s2b += __shfl_xor_sync(0xFFFFFFFFu, s2b, off);
            }
            if (qc == 0) {
                if (ra < N) g_s12[ra] = make_float2(s1a, s2a);
                if (rb < N) g_s12[rb] = make_float2(s1b, s2b);
            }
        }
    }
}

// ---------------------------------------------------------------------------
// Edge attention: one warp = 8 edges. Two LDG.128 fetch 256 node ids;
// each lane gathers 8 float2 (one 8B gather per incidence — minimal);
// reduce over 8-lane groups (3 shuffles).
// ---------------------------------------------------------------------------
__global__ __launch_bounds__(256)
void edge_attn_kernel(const int* __restrict__ nodes,
                      float* __restrict__ ea_out,
                      int H)
{
    int gw   = (blockIdx.x * 256 + threadIdx.x) >> 5;
    int lane = threadIdx.x & 31;
    int e0   = gw * 8;
    if (e0 >= H) return;

    if (e0 + 8 <= H) {
        const int4* base = reinterpret_cast<const int4*>(nodes + (size_t)e0 * DEG);
        int4 n0 = base[lane];        // edge e0 +     (lane>>3), ranks r0..r0+3
        int4 n1 = base[32 + lane];   // edge e0 + 4 + (lane>>3), ranks r0..r0+3
        int r0 = (lane & 7) * 4;

        float2 s00 = g_s12[n0.x], s01 = g_s12[n0.y];
        float2 s02 = g_s12[n0.z], s03 = g_s12[n0.w];
        float2 s10 = g_s12[n1.x], s11 = g_s12[n1.y];
        float2 s12v = g_s12[n1.z], s13 = g_s12[n1.w];

        float fl = (float)(31 - r0), fr = (float)r0;
        float v0 = s00.x * fl         + s00.y * fr
                 + s01.x * (fl - 1.f) + s01.y * (fr + 1.f)
                 + s02.x * (fl - 2.f) + s02.y * (fr + 2.f)
                 + s03.x * (fl - 3.f) + s03.y * (fr + 3.f);
        float v1 = s10.x * fl         + s10.y * fr
                 + s11.x * (fl - 1.f) + s11.y * (fr + 1.f)
                 + s12v.x * (fl - 2.f) + s12v.y * (fr + 2.f)
                 + s13.x * (fl - 3.f) + s13.y * (fr + 3.f);

#pragma unroll
        for (int off = 1; off <= 4; off <<= 1) {
            v0 += __shfl_xor_sync(0xFFFFFFFFu, v0, off);
            v1 += __shfl_xor_sync(0xFFFFFFFFu, v1, off);
        }
        if ((lane & 7) == 0) {
            int eg = e0 + (lane >> 3);
            ea_out[eg]     = v0 * (1.0f / NPAIRS);
            ea_out[eg + 4] = v1 * (1.0f / NPAIRS);
        }
    } else {
        for (int i = 0; i < 8; ++i) {
            int e = e0 + i;
            if (e >= H) break;
            int node = nodes[(size_t)e * DEG + lane];
            float2 s = g_s12[node];
            float v = s.x * (float)(DEG - 1 - lane) + s.y * (float)lane;
#pragma unroll
            for (int off = 16; off > 0; off >>= 1)
                v += __shfl_xor_sync(0xFFFFFFFFu, v, off);
            if (lane == 0) ea_out[e] = v * (1.0f / NPAIRS);
        }
    }
}

// ---------------------------------------------------------------------------
extern "C" void kernel_launch(void* const* d_in, const int* in_sizes, int n_in,
                              void* d_out, int out_size)
{
    const float* x    = (const float*)d_in[0];
    const float* W    = (const float*)d_in[1];
    const float* a    = (const float*)d_in[2];
    const int*   hidx = (const int*)d_in[3];

    int N = in_sizes[0] / F_IN;    // 200000
    int E = in_sizes[3] / 2;       // 1,600,000
    int H = E / DEG;               // 50000

    float* h_out  = (float*)d_out;
    float* ea_out = (float*)d_out + (size_t)N * F_OUT;
    const int* nodes = hidx;

    int sms = 0;
    cudaDeviceGetAttribute(&sms, cudaDevAttrMultiProcessorCount, 0);
    if (sms <= 0) sms = 148;

    cudaFuncSetAttribute(gemm_persist_kernel,
                         cudaFuncAttributeMaxDynamicSharedMemorySize, SM_TOTAL);

    int tiles = (N + TILE_M - 1) / TILE_M;    // 1563
    gemm_persist_kernel<<<sms, 256, SM_TOTAL>>>(x, W, a, h_out, N, tiles);

    {
        int warps  = (H + 7) / 8;             // 6250
        int blocks = (warps * 32 + 255) / 256;
        edge_attn_kernel<<<blocks, 256>>>(nodes, ea_out, H);
    }
}

// round 16
// speedup vs baseline: 1.1750x; 1.0453x over previous
#include <cuda_runtime.h>
#include <cuda_fp16.h>
#include <cstdint>

// ---------------------------------------------------------------------------
// HypergraphAttentionLayer on GB300 (sm_103a), portable-PTX tensor path.
//   h ~= fp16(x) * fp16(W)   (1-chain fp16 HMMA)
//   s1/s2 fused in epilogue; ea[e] = (sum_r s1*(31-r)+s2*r)/496
// R15 winner + full streaming-policy sweep: every touch-once stream
// (x via cp.async L2::evict_first, h via st.cs, nodes via ld.cs, ea via
// st.cs) is marked evict-first; reused data (W, A, g_s12) stays default.
// ---------------------------------------------------------------------------

#define F_IN   128
#define F_OUT  64
#define DEG    32
#define NPAIRS 496.0f
#define MAX_N  200704
#define TILE_M 128
#define PITCHW 68       // 32-bit words per fp16 smem row (64 + 4 pad)
#define PITCHB 272      // bytes per fp16 smem row

__device__ float2 g_s12[MAX_N];

// smem byte offsets
#define SM_AVEC 0                        // 512 B
#define SM_B    512                      // 64*272  = 17408 (fp16 W)
#define SM_A    (SM_B + 17408)           // 128*272 = 34816 (fp16 x)
#define SM_X0   (SM_A + 34816)           // 8 warps * 2 bufs * 8192 = 131072
#define SM_TOTAL (SM_X0 + 131072)        // 183808 B -> 1 CTA/SM

__device__ __forceinline__ uint32_t smem_u32(const void* p) {
    uint32_t a;
    asm("{ .reg .u64 t; cvta.to.shared.u64 t, %1; cvt.u32.u64 %0, t; }"
        : "=r"(a) : "l"(p));
    return a;
}

__device__ __forceinline__ void mma_f16(float c[4],
                                        uint32_t a0, uint32_t a1,
                                        uint32_t a2, uint32_t a3,
                                        uint32_t b0, uint32_t b1)
{
    asm volatile(
        "mma.sync.aligned.m16n8k16.row.col.f32.f16.f16.f32 "
        "{%0,%1,%2,%3}, {%4,%5,%6,%7}, {%8,%9}, {%0,%1,%2,%3};"
        : "+f"(c[0]), "+f"(c[1]), "+f"(c[2]), "+f"(c[3])
        : "r"(a0), "r"(a1), "r"(a2), "r"(a3), "r"(b0), "r"(b1));
}

__device__ __forceinline__ void ldmatrix_x4(uint32_t& r0, uint32_t& r1,
                                            uint32_t& r2, uint32_t& r3,
                                            uint32_t addr)
{
    asm volatile(
        "ldmatrix.sync.aligned.m8n8.x4.shared.b16 {%0,%1,%2,%3}, [%4];"
        : "=r"(r0), "=r"(r1), "=r"(r2), "=r"(r3) : "r"(addr));
}

__device__ __forceinline__ uint2 pack_h4(float4 v) {
    __half2 p01 = __floats2half2_rn(v.x, v.y);
    __half2 p23 = __floats2half2_rn(v.z, v.w);
    uint2 pk;
    pk.x = *reinterpret_cast<uint32_t*>(&p01);
    pk.y = *reinterpret_cast<uint32_t*>(&p23);
    return pk;
}

// streaming (evict-first) float2 store for the write-once h tensor
__device__ __forceinline__ void stg_cs_f2(float* p, float lo, float hi) {
    asm volatile("st.global.cs.v2.f32 [%0], {%1, %2};"
                 :: "l"(p), "f"(lo), "f"(hi) : "memory");
}

// ---------------------------------------------------------------------------
// Persistent GEMM: grid = #SMs, 256 threads (8 warps). Warp w owns rows
// [t*128 + w*16, +16); self-pipelined cp.async; B frags in registers.
// ---------------------------------------------------------------------------
__global__ __launch_bounds__(256, 1)
void gemm_persist_kernel(const float* __restrict__ x,
                         const float* __restrict__ W,
                         const float* __restrict__ a,
                         float* __restrict__ h_out,
                         int N, int tiles)
{
    extern __shared__ char smem[];
    float*    As = reinterpret_cast<float*>(smem + SM_AVEC);
    uint32_t* B  = reinterpret_cast<uint32_t*>(smem + SM_B);
    uint32_t* A  = reinterpret_cast<uint32_t*>(smem + SM_A);

    const int tid  = threadIdx.x;
    const int wid  = tid >> 5;
    const int lane = tid & 31;
    const int qr   = lane >> 2;
    const int qc   = lane & 3;
    const int g    = gridDim.x;

    const uint32_t xw_u32 = smem_u32(smem + SM_X0) + (uint32_t)wid * 16384u;

    // L2 evict-first policy for the read-once x stream
    uint64_t pol;
    asm volatile("createpolicy.fractional.L2::evict_first.b64 %0, 1.0;"
                 : "=l"(pol));

    auto issue_copy = [&](int row0, int b) {
        uint32_t base = xw_u32 + (uint32_t)b * 8192u;
        int r0 = row0 + wid * 16;
#pragma unroll
        for (int it = 0; it < 16; ++it) {
            int idx = it * 32 + lane;
            int rg  = r0 + (idx >> 5);
            if (rg >= N) rg = N - 1;
            const float4* src =
                reinterpret_cast<const float4*>(x) + (size_t)rg * 32 + (idx & 31);
            asm volatile(
                "cp.async.cg.shared.global.L2::cache_hint [%0], [%1], 16, %2;"
                :: "r"(base + (uint32_t)idx * 16u), "l"(src), "l"(pol)
                : "memory");
        }
        asm volatile("cp.async.commit_group;" ::: "memory");
    };

    if (blockIdx.x < tiles)     issue_copy(blockIdx.x * TILE_M, 0);
    if (blockIdx.x + g < tiles) issue_copy((blockIdx.x + g) * TILE_M, 1);

    // ---- W (64x128 fp32) -> fp16 smem, once per CTA ----
#pragma unroll
    for (int it = 0; it < 8; ++it) {
        int idx = it * 256 + tid;
        int n   = idx >> 5;
        int c4  = idx & 31;
        float4 v = reinterpret_cast<const float4*>(W)[n * 32 + c4];
        *reinterpret_cast<uint2*>(B + n * PITCHW + c4 * 2) = pack_h4(v);
    }
    if (tid < 2 * F_OUT) As[tid] = a[tid];
    __syncthreads();

    // ---- all B fragments -> registers (held for whole kernel) ----
    uint32_t bf[8][8][2];
    {
        int rowselB  = (lane & 7) + ((lane >> 4) & 1) * 8;
        int byteselB = ((lane >> 3) & 1) * 16;
        uint32_t b_base = smem_u32(smem + SM_B) + rowselB * PITCHB + byteselB;
#pragma unroll
        for (int jp = 0; jp < 4; ++jp)
#pragma unroll
            for (int kk = 0; kk < 8; ++kk)
                ldmatrix_x4(bf[kk][2 * jp][0], bf[kk][2 * jp][1],
                            bf[kk][2 * jp + 1][0], bf[kk][2 * jp + 1][1],
                            b_base + jp * 16 * PITCHB + kk * 32);
    }

    const int rowselA  = (lane & 7) + ((lane >> 3) & 1) * 8;
    const int byteselA = ((lane >> 4) & 1) * 16;
    const uint32_t a_base = smem_u32(smem + SM_A) +
        (wid * 16 + rowselA) * PITCHB + byteselA;

    // ---- warp-autonomous persistent loop ----
    int buf = 0;
    for (int t = blockIdx.x; t < tiles; t += g, buf ^= 1) {
        const int row0 = t * TILE_M;

        if (t + g < tiles)
            asm volatile("cp.async.wait_group 1;" ::: "memory");
        else
            asm volatile("cp.async.wait_group 0;" ::: "memory");

        // convert my Xraw[buf] -> my A slice
        const float4* Xb = reinterpret_cast<const float4*>(
            smem + SM_X0 + wid * 16384 + buf * 8192);
        uint32_t* Aw = A + wid * 16 * PITCHW;
#pragma unroll
        for (int it = 0; it < 16; ++it) {
            int idx = it * 32 + lane;
            *reinterpret_cast<uint2*>(
                Aw + (idx >> 5) * PITCHW + (idx & 31) * 2) = pack_h4(Xb[idx]);
        }
        __syncwarp();

        if (t + 2 * g < tiles) issue_copy((t + 2 * g) * TILE_M, buf);

        // ---- MMA: ldmatrix A frags, B frags from registers ----
        float c[8][4];
#pragma unroll
        for (int j = 0; j < 8; ++j)
#pragma unroll
            for (int q = 0; q < 4; ++q) c[j][q] = 0.f;

#pragma unroll
        for (int kk = 0; kk < 8; ++kk) {
            uint32_t a0, a1, a2, a3;
            ldmatrix_x4(a0, a1, a2, a3, a_base + kk * 32);
#pragma unroll
            for (int j = 0; j < 8; ++j)
                mma_f16(c[j], a0, a1, a2, a3, bf[kk][j][0], bf[kk][j][1]);
        }

        // ---- epilogue: write h (streaming), fold s1/s2 ----
        {
            float s1a = 0.f, s2a = 0.f, s1b = 0.f, s2b = 0.f;
            int ra = row0 + wid * 16 + qr;
            int rb = ra + 8;
#pragma unroll
            for (int j = 0; j < 8; ++j) {
                int n = j * 8 + qc * 2;
                float a1v = As[n],         a2v = As[n + 1];
                float b1v = As[F_OUT + n], b2v = As[F_OUT + n + 1];
                float* cc = c[j];
                if (ra < N)
                    stg_cs_f2(h_out + (size_t)ra * F_OUT + n, cc[0], cc[1]);
                if (rb < N)
                    stg_cs_f2(h_out + (size_t)rb * F_OUT + n, cc[2], cc[3]);
                s1a = fmaf(cc[0], a1v, fmaf(cc[1], a2v, s1a));
                s2a = fmaf(cc[0], b1v, fmaf(cc[1], b2v, s2a));
                s1b = fmaf(cc[2], a1v, fmaf(cc[3], a2v, s1b));
                s2b = fmaf(cc[2], b1v, fmaf(cc[3], b2v, s2b));
            }
#pragma unroll
            for (int off = 1; off <= 2; off <<= 1) {
                s1a += __shfl_xor_sync(0xFFFFFFFFu, s1a, off);
                s2a += __shfl_xor_sync(0xFFFFFFFFu, s2a, off);
                s1b += __shfl_xor_sync(0xFFFFFFFFu, s1b, off);
                s2b += __shfl_xor_sync(0xFFFFFFFFu, s2b, off);
            }
            if (qc == 0) {
                if (ra < N) g_s12[ra] = make_float2(s1a, s2a);
                if (rb < N) g_s12[rb] = make_float2(s1b, s2b);
            }
        }
    }
}

// ---------------------------------------------------------------------------
// Edge attention: one warp = 8 edges. Index loads + ea stores streaming;
// g_s12 gathers default (reused across edges, L2-resident).
// ---------------------------------------------------------------------------
__global__ __launch_bounds__(256)
void edge_attn_kernel(const int* __restrict__ nodes,
                      float* __restrict__ ea_out,
                      int H)
{
    int gw   = (blockIdx.x * 256 + threadIdx.x) >> 5;
    int lane = threadIdx.x & 31;
    int e0   = gw * 8;
    if (e0 >= H) return;

    if (e0 + 8 <= H) {
        const int4* base = reinterpret_cast<const int4*>(nodes + (size_t)e0 * DEG);
        int4 n0 = __ldcs(base + lane);
        int4 n1 = __ldcs(base + 32 + lane);
        int r0 = (lane & 7) * 4;

        float2 s00 = g_s12[n0.x], s01 = g_s12[n0.y];
        float2 s02 = g_s12[n0.z], s03 = g_s12[n0.w];
        float2 s10 = g_s12[n1.x], s11 = g_s12[n1.y];
        float2 s12v = g_s12[n1.z], s13 = g_s12[n1.w];

        float fl = (float)(31 - r0), fr = (float)r0;
        float v0 = s00.x * fl         + s00.y * fr
                 + s01.x * (fl - 1.f) + s01.y * (fr + 1.f)
                 + s02.x * (fl - 2.f) + s02.y * (fr + 2.f)
                 + s03.x * (fl - 3.f) + s03.y * (fr + 3.f);
        float v1 = s10.x * fl         + s10.y * fr
                 + s11.x * (fl - 1.f) + s11.y * (fr + 1.f)
                 + s12v.x * (fl - 2.f) + s12v.y * (fr + 2.f)
                 + s13.x * (fl - 3.f) + s13.y * (fr + 3.f);

#pragma unroll
        for (int off = 1; off <= 4; off <<= 1) {
            v0 += __shfl_xor_sync(0xFFFFFFFFu, v0, off);
            v1 += __shfl_xor_sync(0xFFFFFFFFu, v1, off);
        }
        if ((lane & 7) == 0) {
            int eg = e0 + (lane >> 3);
            __stcs(ea_out + eg,     v0 * (1.0f / NPAIRS));
            __stcs(ea_out + eg + 4, v1 * (1.0f / NPAIRS));
        }
    } else {
        for (int i = 0; i < 8; ++i) {
            int e = e0 + i;
            if (e >= H) break;
            int node = nodes[(size_t)e * DEG + lane];
            float2 s = g_s12[node];
            float v = s.x * (float)(DEG - 1 - lane) + s.y * (float)lane;
#pragma unroll
            for (int off = 16; off > 0; off >>= 1)
                v += __shfl_xor_sync(0xFFFFFFFFu, v, off);
            if (lane == 0) ea_out[e] = v * (1.0f / NPAIRS);
        }
    }
}

// ---------------------------------------------------------------------------
extern "C" void kernel_launch(void* const* d_in, const int* in_sizes, int n_in,
                              void* d_out, int out_size)
{
    const float* x    = (const float*)d_in[0];
    const float* W    = (const float*)d_in[1];
    const float* a    = (const float*)d_in[2];
    const int*   hidx = (const int*)d_in[3];

    int N = in_sizes[0] / F_IN;    // 200000
    int E = in_sizes[3] / 2;       // 1,600,000
    int H = E / DEG;               // 50000

    float* h_out  = (float*)d_out;
    float* ea_out = (float*)d_out + (size_t)N * F_OUT;
    const int* nodes = hidx;

    int sms = 0;
    cudaDeviceGetAttribute(&sms, cudaDevAttrMultiProcessorCount, 0);
    if (sms <= 0) sms = 148;

    cudaFuncSetAttribute(gemm_persist_kernel,
                         cudaFuncAttributeMaxDynamicSharedMemorySize, SM_TOTAL);

    int tiles = (N + TILE_M - 1) / TILE_M;    // 1563
    gemm_persist_kernel<<<sms, 256, SM_TOTAL>>>(x, W, a, h_out, N, tiles);

    {
        int warps  = (H + 7) / 8;             // 6250
        int blocks = (warps * 32 + 255) / 256;
        edge_attn_kernel<<<blocks, 256>>>(nodes, ea_out, H);
    }
}